// round 1
// baseline (speedup 1.0000x reference)
#include <cuda_runtime.h>
#include <math.h>
#include <stdint.h>

// ---------------- problem constants ----------------
#define BATCH   2
#define SEQ     1024
#define DM      1024          // D_MODEL
#define DI      2048          // D_INNER
#define DS      16            // D_STATE
#define DCONV   4
#define DTR     64            // DT_RANK
#define MROWS   (BATCH*SEQ)   // 2048

// ---------------- scratch (device globals; no allocation allowed) ----------------
__device__ __align__(16) float g_xin [MROWS*DI];   // x_in  (B,S,DI)
__device__ __align__(16) float g_z   [MROWS*DI];   // z     (B,S,DI)
__device__ __align__(16) float g_xact[MROWS*DI];   // silu(conv(x_in))
__device__ __align__(16) float g_ssmp[MROWS*96];   // [dt_r(64) | B(16) | C(16)]
__device__ __align__(16) float g_dt  [MROWS*DI];   // softplus(dt_r@W_dt + b_dt)
__device__ __align__(16) float g_u   [MROWS*DI];   // (y + x_in*D)*silu(z)

// ---------------- generic fp32 SGEMM: C[M,N] = A[M,K] * B[K,N] ----------------
// MODE 0: plain store
// MODE 1: split columns: col<DI -> C (x_in), else -> C2 (z), both ld=DI
// MODE 2: v += bias[n]; softplus
#define BM 128
#define BN 128
#define BK 8

template<int MODE>
__global__ __launch_bounds__(256)
void sgemm_kernel(const float* __restrict__ A, const float* __restrict__ Bm,
                  float* __restrict__ C, float* __restrict__ C2,
                  const float* __restrict__ bias,
                  int M, int N, int K, int lda, int ldb, int ldc)
{
    __shared__ float As[BK][BM];
    __shared__ float Bs[BK][BN];

    const int tid   = threadIdx.x;           // 256 threads
    const int mBase = blockIdx.y * BM;
    const int nBase = blockIdx.x * BN;

    const int aRow = tid >> 1;               // 0..127
    const int aK   = (tid & 1) * 4;          // 0 or 4
    const int bK   = tid >> 5;               // 0..7
    const int bCol = (tid & 31) * 4;         // 0..124

    const int tr = tid >> 4;                 // 0..15 (row tile)
    const int tc = tid & 15;                 // 0..15 (col tile)

    float acc[8][8];
#pragma unroll
    for (int i = 0; i < 8; i++)
#pragma unroll
        for (int j = 0; j < 8; j++) acc[i][j] = 0.f;

    for (int k0 = 0; k0 < K; k0 += BK) {
        // A tile (transposed store into As[k][m])
        float4 av = *reinterpret_cast<const float4*>(
            &A[(size_t)(mBase + aRow) * lda + k0 + aK]);
        As[aK + 0][aRow] = av.x;
        As[aK + 1][aRow] = av.y;
        As[aK + 2][aRow] = av.z;
        As[aK + 3][aRow] = av.w;

        // B tile (predicated on N for the N=96 case)
        float4 bv = make_float4(0.f, 0.f, 0.f, 0.f);
        if (nBase + bCol < N)
            bv = *reinterpret_cast<const float4*>(
                &Bm[(size_t)(k0 + bK) * ldb + nBase + bCol]);
        *reinterpret_cast<float4*>(&Bs[bK][bCol]) = bv;

        __syncthreads();

#pragma unroll
        for (int kk = 0; kk < BK; kk++) {
            float a[8], b[8];
#pragma unroll
            for (int i = 0; i < 8; i++) a[i] = As[kk][tr * 8 + i];
#pragma unroll
            for (int j = 0; j < 8; j++) b[j] = Bs[kk][tc * 8 + j];
#pragma unroll
            for (int i = 0; i < 8; i++)
#pragma unroll
                for (int j = 0; j < 8; j++)
                    acc[i][j] = fmaf(a[i], b[j], acc[i][j]);
        }
        __syncthreads();
    }

#pragma unroll
    for (int i = 0; i < 8; i++) {
        const int gm = mBase + tr * 8 + i;   // M always multiple of 128 here
#pragma unroll
        for (int j = 0; j < 8; j++) {
            const int gn = nBase + tc * 8 + j;
            if (gn >= N) continue;
            float v = acc[i][j];
            if (MODE == 0) {
                C[(size_t)gm * ldc + gn] = v;
            } else if (MODE == 1) {
                if (gn < DI) C [(size_t)gm * DI + gn]        = v;
                else         C2[(size_t)gm * DI + (gn - DI)] = v;
            } else { // MODE == 2 : bias + softplus
                v += bias[gn];
                v = (v > 20.f) ? v : log1pf(expf(v));
                C[(size_t)gm * ldc + gn] = v;
            }
        }
    }
}

// ---------------- depthwise causal conv (width 4) + bias + silu ----------------
__global__ __launch_bounds__(256)
void conv_silu_kernel(const float* __restrict__ xin,
                      const float* __restrict__ w,     // (DI,4)
                      const float* __restrict__ bconv, // (DI)
                      float* __restrict__ xact)
{
    int idx = blockIdx.x * blockDim.x + threadIdx.x;
    if (idx >= MROWS * DI) return;
    const int n  = idx % DI;
    const int bs = idx / DI;
    const int s  = bs % SEQ;

    float acc = bconv[n];
#pragma unroll
    for (int k = 0; k < DCONV; k++) {
        const int ss = s - (DCONV - 1) + k;      // causal, left pad 3
        if (ss >= 0)
            acc = fmaf(xin[idx + (ss - s) * DI], w[n * DCONV + k], acc);
    }
    // silu
    xact[idx] = acc / (1.f + expf(-acc));
}

// ---------------- selective scan ----------------
// One thread per (b, n, j): j = state index. 16 lanes form one channel group.
// h_{s+1} = exp(dt*A_j)*h_s + dt*xa*B_j ; y = sum_j h_j * C_j  (shfl reduce)
// u = (y + x_in*D) * silu(z) fused. Also writes h_last.
__global__ __launch_bounds__(256)
void scan_kernel(const float* __restrict__ ssmp,
                 const float* __restrict__ dt,
                 const float* __restrict__ xact,
                 const float* __restrict__ xin,
                 const float* __restrict__ z,
                 const float* __restrict__ A_log,
                 const float* __restrict__ Dvec,
                 float* __restrict__ u,
                 float* __restrict__ hlast)
{
    const int tid = threadIdx.x;
    const int j = tid & 15;          // state
    const int g = tid >> 4;          // channel within block (0..15)
    const int b = blockIdx.x >> 7;   // 128 blocks per batch
    const int n = ((blockIdx.x & 127) << 4) + g;

    const float Aj = -expf(A_log[n * DS + j]);
    const float Dn = Dvec[n];

    const float* sp  = ssmp + (size_t)b * SEQ * 96;
    const float* dtp = dt   + (size_t)b * SEQ * DI + n;
    const float* xap = xact + (size_t)b * SEQ * DI + n;
    const float* xip = xin  + (size_t)b * SEQ * DI + n;
    const float* zp  = z    + (size_t)b * SEQ * DI + n;
    float*       up  = u    + (size_t)b * SEQ * DI + n;

    float h = 0.f;
    for (int s = 0; s < SEQ; s++) {
        const float Bv  = sp[s * 96 + DTR + j];        // B[b,s,j]
        const float Cv  = sp[s * 96 + DTR + DS + j];   // C[b,s,j]
        const float dtv = dtp[s * DI];
        const float xa  = xap[s * DI];

        const float dA = expf(dtv * Aj);               // off the dep chain
        h = fmaf(dA, h, dtv * xa * Bv);                // 1 FFMA on chain

        float y = h * Cv;
        y += __shfl_xor_sync(0xffffffffu, y, 8);
        y += __shfl_xor_sync(0xffffffffu, y, 4);
        y += __shfl_xor_sync(0xffffffffu, y, 2);
        y += __shfl_xor_sync(0xffffffffu, y, 1);

        if (j == 0) {
            const float zi = zp[s * DI];
            const float ui = (y + xip[s * DI] * Dn) * (zi / (1.f + expf(-zi)));
            up[s * DI] = ui;
        }
    }
    hlast[((size_t)b * DI + n) * DS + j] = h;
}

// ---------------- launcher ----------------
extern "C" void kernel_launch(void* const* d_in, const int* in_sizes, int n_in,
                              void* d_out, int out_size)
{
    const float* x      = (const float*)d_in[0];   // (B,S,DM)
    const float* W_in   = (const float*)d_in[1];   // (DM, 2*DI)
    const float* conv_w = (const float*)d_in[2];   // (DI, 4)
    const float* conv_b = (const float*)d_in[3];   // (DI)
    const float* W_x    = (const float*)d_in[4];   // (DI, 96)
    const float* W_dt   = (const float*)d_in[5];   // (DTR, DI)
    const float* b_dt   = (const float*)d_in[6];   // (DI)
    const float* A_log  = (const float*)d_in[7];   // (DI, DS)
    const float* Dvec   = (const float*)d_in[8];   // (DI)
    const float* W_out  = (const float*)d_in[9];   // (DI, DM)

    float* out = (float*)d_out;                    // (B,S,DM) then h_last

    float *xin, *zb, *xact, *ssmp, *dtb, *ub;
    cudaGetSymbolAddress((void**)&xin,  g_xin);
    cudaGetSymbolAddress((void**)&zb,   g_z);
    cudaGetSymbolAddress((void**)&xact, g_xact);
    cudaGetSymbolAddress((void**)&ssmp, g_ssmp);
    cudaGetSymbolAddress((void**)&dtb,  g_dt);
    cudaGetSymbolAddress((void**)&ub,   g_u);

    // h_last destination (only if harness expects the tuple concatenation)
    float* hlast = out + (size_t)MROWS * DM;
    bool write_hlast = (out_size >= MROWS * DM + BATCH * DI * DS);
    if (!write_hlast) hlast = ub;  // harmless dump target

    // 1) xz = x @ W_in, split into x_in / z
    sgemm_kernel<1><<<dim3((2 * DI) / BN, MROWS / BM), 256>>>(
        x, W_in, xin, zb, nullptr, MROWS, 2 * DI, DM, DM, 2 * DI, 0);

    // 2) causal depthwise conv + silu
    conv_silu_kernel<<<(MROWS * DI + 255) / 256, 256>>>(xin, conv_w, conv_b, xact);

    // 3) ssm_p = x_act @ W_x  (N=96, predicated)
    sgemm_kernel<0><<<dim3(1, MROWS / BM), 256>>>(
        xact, W_x, ssmp, nullptr, nullptr, MROWS, 96, DI, DI, 96, 96);

    // 4) dt = softplus(dt_r @ W_dt + b_dt)   (A = ssmp cols [0,64), lda=96)
    sgemm_kernel<2><<<dim3(DI / BN, MROWS / BM), 256>>>(
        ssmp, W_dt, dtb, nullptr, b_dt, MROWS, DI, DTR, 96, DI, DI);

    // 5) selective scan + output gating -> u, h_last
    scan_kernel<<<BATCH * (DI / 16), 256>>>(
        ssmp, dtb, xact, xin, zb, A_log, Dvec, ub, hlast);

    // 6) out = u @ W_out
    sgemm_kernel<0><<<dim3(DM / BN, MROWS / BM), 256>>>(
        ub, W_out, out, nullptr, nullptr, MROWS, DM, DI, DI, DM, DM);
}

// round 2
// speedup vs baseline: 1.6504x; 1.6504x over previous
#include <cuda_runtime.h>
#include <math.h>
#include <stdint.h>

// ---------------- problem constants ----------------
#define BATCH   2
#define SEQ     1024
#define DM      1024          // D_MODEL
#define DI      2048          // D_INNER
#define DS      16            // D_STATE
#define DCONV   4
#define DTR     64            // DT_RANK
#define MROWS   (BATCH*SEQ)   // 2048

// ---------------- scratch (device globals; no allocation allowed) ----------------
__device__ __align__(16) float g_xin [MROWS*DI];   // x_in  (B,S,DI)
__device__ __align__(16) float g_z   [MROWS*DI];   // z     (B,S,DI)
__device__ __align__(16) float g_xact[MROWS*DI];   // silu(conv(x_in))
__device__ __align__(16) float g_ssmp[MROWS*96];   // [dt_r(64) | B(16) | C(16)]
__device__ __align__(16) float g_dt  [MROWS*DI];   // softplus(dt_r@W_dt + b_dt)
__device__ __align__(16) float g_u   [MROWS*DI];   // (y + x_in*D)*silu(z)

// ---------------- tf32 helpers ----------------
__device__ __forceinline__ float to_tf32(float f) {
    uint32_t u;
    asm("cvt.rna.tf32.f32 %0, %1;" : "=r"(u) : "f"(f));
    return __uint_as_float(u);
}

__device__ __forceinline__ void mma_tf32(float* c, const uint32_t* a, const uint32_t* b) {
    asm volatile(
        "mma.sync.aligned.m16n8k8.row.col.f32.tf32.tf32.f32 "
        "{%0,%1,%2,%3}, {%4,%5,%6,%7}, {%8,%9}, {%0,%1,%2,%3};\n"
        : "+f"(c[0]), "+f"(c[1]), "+f"(c[2]), "+f"(c[3])
        : "r"(a[0]), "r"(a[1]), "r"(a[2]), "r"(a[3]), "r"(b[0]), "r"(b[1]));
}

// ---------------- tf32 tensor-core GEMM: C[M,N] = A[M,K] * B[K,N] ----------------
// Block tile 128x128x32, 256 threads = 8 warps (2 x 4), warp tile 64x32.
// MODE 0: plain store
// MODE 1: split columns: col<DI -> C (x_in), else -> C2 (z), both ld=DI
// MODE 2: v += bias[n]; softplus
// MODE 3: atomicAdd (split-K); C must be zeroed beforehand
#define TBM 128
#define TBN 128
#define TBK 32
#define ASTR 36    // TBK + 4 : fragment banks = lane (conflict-free)
#define BSTR 136   // TBN + 8 : fragment banks = 8*tq + g (conflict-free)

template<int MODE>
__global__ __launch_bounds__(256)
void tgemm_kernel(const float* __restrict__ A, const float* __restrict__ B,
                  float* __restrict__ C, float* __restrict__ C2,
                  const float* __restrict__ bias,
                  int M, int N, int K, int lda, int ldb, int ldc)
{
    __shared__ float As[TBM][ASTR];
    __shared__ float Bs[TBK][BSTR];

    const int tid   = threadIdx.x;
    const int lane  = tid & 31;
    const int warp  = tid >> 5;
    const int wm    = warp >> 2;          // 0..1
    const int wn    = warp & 3;           // 0..3
    const int g     = lane >> 2;          // 0..7
    const int tq    = lane & 3;           // 0..3

    const int mBase = blockIdx.y * TBM;
    const int nBase = blockIdx.x * TBN;

    // split-K range (MODE 3 uses gridDim.z parts)
    const int kPer   = K / gridDim.z;
    const int kBegin = blockIdx.z * kPer;
    const int kEnd   = kBegin + kPer;

    float acc[4][4][4];
#pragma unroll
    for (int i = 0; i < 4; i++)
#pragma unroll
        for (int j = 0; j < 4; j++) {
            acc[i][j][0] = 0.f; acc[i][j][1] = 0.f;
            acc[i][j][2] = 0.f; acc[i][j][3] = 0.f;
        }

    for (int k0 = kBegin; k0 < kEnd; k0 += TBK) {
        // ---- fill A tile: 128 x 32 (row-major, tf32-rounded) ----
#pragma unroll
        for (int i = 0; i < 4; i++) {
            const int idx = i * 256 + tid;        // 0..1023
            const int r   = idx >> 3;             // 0..127
            const int c   = (idx & 7) << 2;       // 0..28
            float4 v = *reinterpret_cast<const float4*>(
                &A[(size_t)(mBase + r) * lda + k0 + c]);
            As[r][c + 0] = to_tf32(v.x);
            As[r][c + 1] = to_tf32(v.y);
            As[r][c + 2] = to_tf32(v.z);
            As[r][c + 3] = to_tf32(v.w);
        }
        // ---- fill B tile: 32 x 128 (row-major = K x N, tf32-rounded) ----
#pragma unroll
        for (int i = 0; i < 4; i++) {
            const int idx = i * 256 + tid;
            const int r   = idx >> 5;             // 0..31
            const int c   = (idx & 31) << 2;      // 0..124
            float4 v = make_float4(0.f, 0.f, 0.f, 0.f);
            if (nBase + c < N)
                v = *reinterpret_cast<const float4*>(
                    &B[(size_t)(k0 + r) * ldb + nBase + c]);
            Bs[r][c + 0] = to_tf32(v.x);
            Bs[r][c + 1] = to_tf32(v.y);
            Bs[r][c + 2] = to_tf32(v.z);
            Bs[r][c + 3] = to_tf32(v.w);
        }
        __syncthreads();

#pragma unroll
        for (int kk = 0; kk < 4; kk++) {          // 4 slices of k=8
            uint32_t a[4][4], b[4][2];
#pragma unroll
            for (int am = 0; am < 4; am++) {
                const int row = wm * 64 + am * 16;
                a[am][0] = __float_as_uint(As[row + g    ][kk * 8 + tq    ]);
                a[am][1] = __float_as_uint(As[row + g + 8][kk * 8 + tq    ]);
                a[am][2] = __float_as_uint(As[row + g    ][kk * 8 + tq + 4]);
                a[am][3] = __float_as_uint(As[row + g + 8][kk * 8 + tq + 4]);
            }
#pragma unroll
            for (int bn = 0; bn < 4; bn++) {
                const int col = wn * 32 + bn * 8 + g;
                b[bn][0] = __float_as_uint(Bs[kk * 8 + tq    ][col]);
                b[bn][1] = __float_as_uint(Bs[kk * 8 + tq + 4][col]);
            }
#pragma unroll
            for (int am = 0; am < 4; am++)
#pragma unroll
                for (int bn = 0; bn < 4; bn++)
                    mma_tf32(acc[am][bn], a[am], b[bn]);
        }
        __syncthreads();
    }

    // ---- epilogue ----
#pragma unroll
    for (int am = 0; am < 4; am++) {
#pragma unroll
        for (int bn = 0; bn < 4; bn++) {
#pragma unroll
            for (int r = 0; r < 4; r++) {
                const int gm = mBase + wm * 64 + am * 16 + g + (r >= 2 ? 8 : 0);
                const int gn = nBase + wn * 32 + bn * 8 + 2 * tq + (r & 1);
                if (gn >= N) continue;
                float v = acc[am][bn][r];
                if (MODE == 0) {
                    C[(size_t)gm * ldc + gn] = v;
                } else if (MODE == 1) {
                    if (gn < DI) C [(size_t)gm * DI + gn]        = v;
                    else         C2[(size_t)gm * DI + (gn - DI)] = v;
                } else if (MODE == 2) {
                    v += bias[gn];
                    v = (v > 20.f) ? v : log1pf(expf(v));
                    C[(size_t)gm * ldc + gn] = v;
                } else { // MODE 3: split-K accumulate
                    atomicAdd(&C[(size_t)gm * ldc + gn], v);
                }
            }
        }
    }
}

// ---------------- depthwise causal conv (width 4) + bias + silu ----------------
__global__ __launch_bounds__(256)
void conv_silu_kernel(const float* __restrict__ xin,
                      const float* __restrict__ w,     // (DI,4)
                      const float* __restrict__ bconv, // (DI)
                      float* __restrict__ xact)
{
    int idx = blockIdx.x * blockDim.x + threadIdx.x;
    if (idx >= MROWS * DI) return;
    const int n  = idx % DI;
    const int bs = idx / DI;
    const int s  = bs % SEQ;

    float acc = bconv[n];
#pragma unroll
    for (int k = 0; k < DCONV; k++) {
        const int ss = s - (DCONV - 1) + k;      // causal, left pad 3
        if (ss >= 0)
            acc = fmaf(xin[idx + (ss - s) * DI], w[n * DCONV + k], acc);
    }
    xact[idx] = acc / (1.f + expf(-acc));
}

// ---------------- selective scan ----------------
__global__ __launch_bounds__(256)
void scan_kernel(const float* __restrict__ ssmp,
                 const float* __restrict__ dt,
                 const float* __restrict__ xact,
                 const float* __restrict__ xin,
                 const float* __restrict__ z,
                 const float* __restrict__ A_log,
                 const float* __restrict__ Dvec,
                 float* __restrict__ u,
                 float* __restrict__ hlast)
{
    const int tid = threadIdx.x;
    const int j = tid & 15;          // state
    const int g = tid >> 4;          // channel within block (0..15)
    const int b = blockIdx.x >> 7;   // 128 blocks per batch
    const int n = ((blockIdx.x & 127) << 4) + g;

    const float Aj = -expf(A_log[n * DS + j]);
    const float Dn = Dvec[n];

    const float* sp  = ssmp + (size_t)b * SEQ * 96;
    const float* dtp = dt   + (size_t)b * SEQ * DI + n;
    const float* xap = xact + (size_t)b * SEQ * DI + n;
    const float* xip = xin  + (size_t)b * SEQ * DI + n;
    const float* zp  = z    + (size_t)b * SEQ * DI + n;
    float*       up  = u    + (size_t)b * SEQ * DI + n;

    float h = 0.f;
    for (int s = 0; s < SEQ; s++) {
        const float Bv  = sp[s * 96 + DTR + j];
        const float Cv  = sp[s * 96 + DTR + DS + j];
        const float dtv = dtp[s * DI];
        const float xa  = xap[s * DI];

        const float dA = expf(dtv * Aj);
        h = fmaf(dA, h, dtv * xa * Bv);

        float y = h * Cv;
        y += __shfl_xor_sync(0xffffffffu, y, 8);
        y += __shfl_xor_sync(0xffffffffu, y, 4);
        y += __shfl_xor_sync(0xffffffffu, y, 2);
        y += __shfl_xor_sync(0xffffffffu, y, 1);

        if (j == 0) {
            const float zi = zp[s * DI];
            const float ui = (y + xip[s * DI] * Dn) * (zi / (1.f + expf(-zi)));
            up[s * DI] = ui;
        }
    }
    hlast[((size_t)b * DI + n) * DS + j] = h;
}

// ---------------- launcher ----------------
extern "C" void kernel_launch(void* const* d_in, const int* in_sizes, int n_in,
                              void* d_out, int out_size)
{
    const float* x      = (const float*)d_in[0];   // (B,S,DM)
    const float* W_in   = (const float*)d_in[1];   // (DM, 2*DI)
    const float* conv_w = (const float*)d_in[2];   // (DI, 4)
    const float* conv_b = (const float*)d_in[3];   // (DI)
    const float* W_x    = (const float*)d_in[4];   // (DI, 96)
    const float* W_dt   = (const float*)d_in[5];   // (DTR, DI)
    const float* b_dt   = (const float*)d_in[6];   // (DI)
    const float* A_log  = (const float*)d_in[7];   // (DI, DS)
    const float* Dvec   = (const float*)d_in[8];   // (DI)
    const float* W_out  = (const float*)d_in[9];   // (DI, DM)

    float* out = (float*)d_out;                    // (B,S,DM) then h_last

    float *xin, *zb, *xact, *ssmp, *dtb, *ub;
    cudaGetSymbolAddress((void**)&xin,  g_xin);
    cudaGetSymbolAddress((void**)&zb,   g_z);
    cudaGetSymbolAddress((void**)&xact, g_xact);
    cudaGetSymbolAddress((void**)&ssmp, g_ssmp);
    cudaGetSymbolAddress((void**)&dtb,  g_dt);
    cudaGetSymbolAddress((void**)&ub,   g_u);

    float* hlast = out + (size_t)MROWS * DM;
    bool write_hlast = (out_size >= MROWS * DM + BATCH * DI * DS);
    if (!write_hlast) hlast = ub;

    // 1) xz = x @ W_in, split into x_in / z
    tgemm_kernel<1><<<dim3((2 * DI) / TBN, MROWS / TBM, 1), 256>>>(
        x, W_in, xin, zb, nullptr, MROWS, 2 * DI, DM, DM, 2 * DI, 0);

    // 2) causal depthwise conv + silu
    conv_silu_kernel<<<(MROWS * DI + 255) / 256, 256>>>(xin, conv_w, conv_b, xact);

    // 3) ssm_p = x_act @ W_x  (N=96, split-K=4 + atomic accumulate)
    cudaMemsetAsync(ssmp, 0, (size_t)MROWS * 96 * sizeof(float));
    tgemm_kernel<3><<<dim3(1, MROWS / TBM, 4), 256>>>(
        xact, W_x, ssmp, nullptr, nullptr, MROWS, 96, DI, DI, 96, 96);

    // 4) dt = softplus(dt_r @ W_dt + b_dt)   (A = ssmp cols [0,64), lda=96)
    tgemm_kernel<2><<<dim3(DI / TBN, MROWS / TBM, 1), 256>>>(
        ssmp, W_dt, dtb, nullptr, b_dt, MROWS, DI, DTR, 96, DI, DI);

    // 5) selective scan + output gating -> u, h_last
    scan_kernel<<<BATCH * (DI / 16), 256>>>(
        ssmp, dtb, xact, xin, zb, A_log, Dvec, ub, hlast);

    // 6) out = u @ W_out
    tgemm_kernel<0><<<dim3(DM / TBN, MROWS / TBM, 1), 256>>>(
        ub, W_out, out, nullptr, nullptr, MROWS, DM, DI, DI, DM, DM);
}